// round 2
// baseline (speedup 1.0000x reference)
#include <cuda_runtime.h>
#include <math.h>

#define HH 1024
#define WW 1024
#define CC 128
#define EPSF 1e-8f

#define COLS_OUT 30           // output columns per block (lanes 1..30)
#define COLS_LOAD 32          // loaded columns incl. halo
#define ROWS_PB 64            // output rows per block
#define VSTRIDE 132           // floats per pixel vector in smem (padded: conflict-free LDS.128)
#define SLOT_FLOATS (COLS_LOAD * VSTRIDE)   // 4224
#define NSLOTS 4
#define NWARPS 8
#define SMEM_FLOATS (NSLOTS * SLOT_FLOATS + NWARPS * 32)

__global__ void __launch_bounds__(256)
cos_sim_box_kernel(const float* __restrict__ in, float* __restrict__ out)
{
    extern __shared__ float smem[];
    float* rowsbuf  = smem;                          // NSLOTS ring of normalized rows
    float* partials = smem + NSLOTS * SLOT_FLOATS;   // [8][32] warp partial dots

    const int tid  = threadIdx.x;
    const int warp = tid >> 5;
    const int lane = tid & 31;
    const int w0   = blockIdx.x * COLS_OUT;          // first output column of this strip
    const int r0   = blockIdx.y * ROWS_PB;

    // ---- load one image row (32 cols incl. halo), normalize, store to smem ring ----
    auto load_row = [&](int hr) {
        const int slot = (hr + 2 * NSLOTS) & (NSLOTS - 1);
        float* dst = rowsbuf + slot * SLOT_FLOATS;
        #pragma unroll
        for (int q = 0; q < 4; q++) {
            const int p  = warp * 4 + q;             // pixel within strip: 0..31
            const int gc = w0 + p - 1;               // global column (halo at p=0, p=31)
            float4 v = make_float4(0.f, 0.f, 0.f, 0.f);
            if (hr >= 0 && hr < HH && gc >= 0 && gc < WW) {
                const float4* g = reinterpret_cast<const float4*>(
                    in + ((size_t)hr * WW + gc) * CC);
                v = g[lane];                         // 512B contiguous per warp
            }
            float ss = v.x * v.x + v.y * v.y + v.z * v.z + v.w * v.w;
            #pragma unroll
            for (int o = 16; o > 0; o >>= 1)
                ss += __shfl_xor_sync(0xffffffffu, ss, o);
            const float nrm = sqrtf(ss);
            const float inv = 1.0f / fmaxf(nrm, EPSF);
            v.x *= inv; v.y *= inv; v.z *= inv; v.w *= inv;
            *reinterpret_cast<float4*>(dst + p * VSTRIDE + lane * 4) = v;
        }
    };

    load_row(r0 - 1);
    load_row(r0);

    for (int h = r0; h < r0 + ROWS_PB; h++) {
        load_row(h + 1);
        __syncthreads();   // ring slot (h+1) published; prior iter's reduce also done

        const float* rm = rowsbuf + (((h - 1) + 2 * NSLOTS) & (NSLOTS - 1)) * SLOT_FLOATS;
        const float* rc = rowsbuf + (((h    ) + 2 * NSLOTS) & (NSLOTS - 1)) * SLOT_FLOATS;
        const float* rp = rowsbuf + (((h + 1) + 2 * NSLOTS) & (NSLOTS - 1)) * SLOT_FLOATS;

        // lane = column within strip; warp owns 16 channels (4 float4 chunks)
        float acc = 0.f;
        const int base = lane * VSTRIDE + warp * 16;
        #pragma unroll
        for (int t = 0; t < 4; t++) {
            const float4 a = *reinterpret_cast<const float4*>(rm + base + t * 4);
            const float4 b = *reinterpret_cast<const float4*>(rc + base + t * 4);
            const float4 c = *reinterpret_cast<const float4*>(rp + base + t * 4);
            float4 v;                                  // vertical 3-sum
            v.x = a.x + b.x + c.x;
            v.y = a.y + b.y + c.y;
            v.z = a.z + b.z + c.z;
            v.w = a.w + b.w + c.w;
            float4 vl, vr;                             // horizontal neighbors via shuffle
            vl.x = __shfl_up_sync(0xffffffffu, v.x, 1);
            vl.y = __shfl_up_sync(0xffffffffu, v.y, 1);
            vl.z = __shfl_up_sync(0xffffffffu, v.z, 1);
            vl.w = __shfl_up_sync(0xffffffffu, v.w, 1);
            vr.x = __shfl_down_sync(0xffffffffu, v.x, 1);
            vr.y = __shfl_down_sync(0xffffffffu, v.y, 1);
            vr.z = __shfl_down_sync(0xffffffffu, v.z, 1);
            vr.w = __shfl_down_sync(0xffffffffu, v.w, 1);
            const float sx = v.x + vl.x + vr.x;        // S = 3x3 box sum of xn
            const float sy = v.y + vl.y + vr.y;
            const float sz = v.z + vl.z + vr.z;
            const float sw = v.w + vl.w + vr.w;
            acc += b.x * sx + b.y * sy + b.z * sz + b.w * sw;  // xn · S (16-ch partial)
        }
        partials[warp * 32 + lane] = acc;
        __syncthreads();

        if (tid < 32) {
            const int wl = tid;
            if (wl >= 1 && wl <= COLS_OUT) {
                const int gc = w0 + wl - 1;
                if (gc < WW) {
                    float s = 0.f;
                    #pragma unroll
                    for (int j = 0; j < NWARPS; j++) s += partials[j * 32 + wl];
                    out[(size_t)h * WW + gc] = s - 1.0f;
                }
            }
        }
        // next iter's first __syncthreads orders the reduce above against
        // the next partials write and the ring-slot reuse.
    }
}

extern "C" void kernel_launch(void* const* d_in, const int* in_sizes, int n_in,
                              void* d_out, int out_size)
{
    const float* in = (const float*)d_in[0];
    float* out = (float*)d_out;

    const size_t smem_bytes = SMEM_FLOATS * sizeof(float);   // ~68.6 KB
    cudaFuncSetAttribute(cos_sim_box_kernel,
                         cudaFuncAttributeMaxDynamicSharedMemorySize,
                         (int)smem_bytes);

    dim3 grid((WW + COLS_OUT - 1) / COLS_OUT, HH / ROWS_PB);  // 35 x 16
    dim3 block(256);
    cos_sim_box_kernel<<<grid, block, smem_bytes>>>(in, out);
}

// round 3
// speedup vs baseline: 1.5150x; 1.5150x over previous
#include <cuda_runtime.h>
#include <math.h>

#define HH 1024
#define WW 1024
#define CC 128
#define SEGW 128          // output columns per warp
#define TPB 256           // 8 warps: 8*128 = 1024 columns = one full row per block

__device__ __forceinline__ float warp_sum(float v) {
    #pragma unroll
    for (int o = 16; o > 0; o >>= 1)
        v += __shfl_xor_sync(0xffffffffu, v, o);
    return v;
}

__global__ void __launch_bounds__(TPB, 2)
cos_sim_rolling(const float* __restrict__ in, float* __restrict__ out)
{
    const int h    = blockIdx.x;
    const int lane = threadIdx.x & 31;
    const int warp = threadIdx.x >> 5;
    const int c0   = warp * SEGW;

    const bool okm = (h > 0);
    const bool okp = (h < HH - 1);
    const float* pm = in + ((size_t)(h - 1) * WW) * CC;   // row h-1 base
    const float* pc = in + ((size_t)(h    ) * WW) * CC;   // row h
    const float* pp = in + ((size_t)(h + 1) * WW) * CC;   // row h+1

    // predicated raw load of the 3-row column c (zero outside the image)
    auto ldraw3 = [&](int c, float4& a, float4& b, float4& cc_) {
        const bool okc = ((unsigned)c < (unsigned)WW);
        const size_t off = (size_t)c * CC + lane * 4;
        a = make_float4(0.f, 0.f, 0.f, 0.f);
        b = a; cc_ = a;
        if (okc) {
            if (okm) a   = *reinterpret_cast<const float4*>(pm + off);
            b            = *reinterpret_cast<const float4*>(pc + off);
            if (okp) cc_ = *reinterpret_cast<const float4*>(pp + off);
        }
    };

    // normalize the 3 vectors of one column, produce vertical sum + center xn
    auto process = [&](float4 a, float4 b, float4 c,
                       float4& vsum, float4& cen) {
        float ssa = a.x*a.x + a.y*a.y + a.z*a.z + a.w*a.w;
        float ssb = b.x*b.x + b.y*b.y + b.z*b.z + b.w*b.w;
        float ssc = c.x*c.x + c.y*c.y + c.z*c.z + c.w*c.w;
        #pragma unroll
        for (int o = 16; o > 0; o >>= 1) {
            ssa += __shfl_xor_sync(0xffffffffu, ssa, o);
            ssb += __shfl_xor_sync(0xffffffffu, ssb, o);
            ssc += __shfl_xor_sync(0xffffffffu, ssc, o);
        }
        // x / max(sqrt(ss), 1e-8)  ==  x * rsqrt(ss) for ss >= 1e-16, else x*1e8
        const float ia = (ssa >= 1e-16f) ? rsqrtf(ssa) : 1e8f;
        const float ib = (ssb >= 1e-16f) ? rsqrtf(ssb) : 1e8f;
        const float ic = (ssc >= 1e-16f) ? rsqrtf(ssc) : 1e8f;
        cen.x = b.x * ib;  cen.y = b.y * ib;  cen.z = b.z * ib;  cen.w = b.w * ib;
        vsum.x = fmaf(a.x, ia, fmaf(c.x, ic, cen.x));
        vsum.y = fmaf(a.y, ia, fmaf(c.y, ic, cen.y));
        vsum.z = fmaf(a.z, ia, fmaf(c.z, ic, cen.z));
        vsum.w = fmaf(a.w, ia, fmaf(c.w, ic, cen.w));
    };

    // ---- preamble: columns c0-1 and c0, prefetch c0+1 and c0+2 ----
    float4 vs_prev, vs_cur, cen_cur, cen_dead;
    {
        float4 a, b, c;
        ldraw3(c0 - 1, a, b, c);
        process(a, b, c, vs_prev, cen_dead);
    }
    {
        float4 a, b, c;
        ldraw3(c0, a, b, c);
        process(a, b, c, vs_cur, cen_cur);
    }
    float4 ra0, rb0, rc0, ra1, rb1, rc1;        // two in-flight stages
    ldraw3(c0 + 1, ra0, rb0, rc0);
    ldraw3(c0 + 2, ra1, rb1, rc1);

    float keep = 0.f;
    float* orow = out + (size_t)h * WW;

    // one pipeline step: consume stage (col j+1), emit sim(j), refill stage (col j+3)
    auto step = [&](int j, float4& a, float4& b, float4& c) {
        float4 vs_next, cen_next;
        process(a, b, c, vs_next, cen_next);
        ldraw3(j + 3, a, b, c);                  // prefetch, 2 steps ahead

        float4 S;
        S.x = vs_prev.x + vs_cur.x + vs_next.x;
        S.y = vs_prev.y + vs_cur.y + vs_next.y;
        S.z = vs_prev.z + vs_cur.z + vs_next.z;
        S.w = vs_prev.w + vs_cur.w + vs_next.w;

        float d = cen_cur.x * S.x;
        d = fmaf(cen_cur.y, S.y, d);
        d = fmaf(cen_cur.z, S.z, d);
        d = fmaf(cen_cur.w, S.w, d);
        d = warp_sum(d);

        keep = ((j & 31) == lane) ? d : keep;
        if ((j & 31) == 31)
            orow[(j & ~31) + lane] = keep - 1.0f;

        vs_prev = vs_cur; vs_cur = vs_next; cen_cur = cen_next;
    };

    #pragma unroll 4
    for (int jj = 0; jj < SEGW; jj += 2) {
        step(c0 + jj,     ra0, rb0, rc0);
        step(c0 + jj + 1, ra1, rb1, rc1);
    }
}

extern "C" void kernel_launch(void* const* d_in, const int* in_sizes, int n_in,
                              void* d_out, int out_size)
{
    const float* in = (const float*)d_in[0];
    float* out = (float*)d_out;
    cos_sim_rolling<<<HH, TPB>>>(in, out);
}

// round 4
// speedup vs baseline: 2.7965x; 1.8459x over previous
#include <cuda_runtime.h>
#include <math.h>

#define HH 1024
#define WW 1024
#define CC 128
#define NW 16                 // warps per block = columns per block (incl. 2 halo)
#define TPB (NW * 32)
#define COUT (NW - 2)         // 14 output columns per block
#define ROWG 128              // rows per block

__global__ void __launch_bounds__(TPB, 2)
cos_sim_stream(const float* __restrict__ in, float* __restrict__ out)
{
    __shared__ float vs[2][NW][CC];   // double-buffered vertical-sum exchange (16 KB)

    const int lane = threadIdx.x & 31;
    const int wid  = threadIdx.x >> 5;
    const int col  = blockIdx.x * COUT + wid - 1;      // wid 0 and NW-1 are halo
    const bool colok = ((unsigned)col < (unsigned)WW);
    const bool outok = colok && (wid >= 1) && (wid <= COUT);
    const int r0 = blockIdx.y * ROWG;

    const float* gcol = in + (size_t)col * CC + lane * 4;
    const size_t rowstep = (size_t)WW * CC;

    // predicated load of pixel (h, col): this lane's 4 channels
    auto ld = [&](int h) -> float4 {
        float4 v = make_float4(0.f, 0.f, 0.f, 0.f);
        if (colok && (unsigned)h < (unsigned)HH)
            v = *reinterpret_cast<const float4*>(gcol + (size_t)h * rowstep);
        return v;
    };
    // normalize: x / max(sqrt(ss), 1e-8)
    auto normv = [&](float4 v) -> float4 {
        float ss = v.x*v.x + v.y*v.y + v.z*v.z + v.w*v.w;
        #pragma unroll
        for (int o = 16; o > 0; o >>= 1)
            ss += __shfl_xor_sync(0xffffffffu, ss, o);
        const float inv = (ss >= 1e-16f) ? rsqrtf(ss) : 1e8f;
        return make_float4(v.x*inv, v.y*inv, v.z*inv, v.w*inv);
    };

    // vertical window in registers: xnA = xn(h-1), xnB = xn(h), xnC = xn(h+1)
    float4 xnA = normv(ld(r0 - 1));
    float4 xnB = normv(ld(r0));
    float4 raw0 = ld(r0 + 1);     // two prefetch stages, 2 rows ahead
    float4 raw1 = ld(r0 + 2);
    float keep = 0.f;

    // one row step: consume a raw stage (row h+1), emit sim(h), refill stage (row h+3)
    auto step = [&](int i, float4& raw) {
        const int h = r0 + i;
        const float4 xnC = normv(raw);
        raw = ld(h + 3);

        float4 v;                                  // vertical 3-sum at (·, col)
        v.x = xnA.x + xnB.x + xnC.x;
        v.y = xnA.y + xnB.y + xnC.y;
        v.z = xnA.z + xnB.z + xnC.z;
        v.w = xnA.w + xnB.w + xnC.w;
        *reinterpret_cast<float4*>(&vs[h & 1][wid][lane * 4]) = v;
        __syncthreads();

        if (wid >= 1 && wid <= COUT) {             // warp-uniform branch
            const float4 l = *reinterpret_cast<const float4*>(&vs[h & 1][wid - 1][lane * 4]);
            const float4 r = *reinterpret_cast<const float4*>(&vs[h & 1][wid + 1][lane * 4]);
            float d;                               // xn(h,col) · 3x3-box-sum
            d =      xnB.x * (l.x + v.x + r.x);
            d = fmaf(xnB.y,  (l.y + v.y + r.y), d);
            d = fmaf(xnB.z,  (l.z + v.z + r.z), d);
            d = fmaf(xnB.w,  (l.w + v.w + r.w), d);
            #pragma unroll
            for (int o = 16; o > 0; o >>= 1)
                d += __shfl_xor_sync(0xffffffffu, d, o);

            keep = ((i & 31) == lane) ? (d - 1.0f) : keep;
            if (((i & 31) == 31) && outok)
                out[(size_t)(h - 31 + lane) * WW + col] = keep;
        }
        xnA = xnB;  xnB = xnC;
    };

    #pragma unroll 2
    for (int i = 0; i < ROWG; i += 2) {
        step(i,     raw0);
        step(i + 1, raw1);
    }
}

extern "C" void kernel_launch(void* const* d_in, const int* in_sizes, int n_in,
                              void* d_out, int out_size)
{
    const float* in = (const float*)d_in[0];
    float* out = (float*)d_out;
    dim3 grid((WW + COUT - 1) / COUT, HH / ROWG);   // 74 x 8
    cos_sim_stream<<<grid, TPB>>>(in, out);
}

// round 5
// speedup vs baseline: 2.8015x; 1.0018x over previous
#include <cuda_runtime.h>
#include <math.h>

#define HH 1024
#define WW 1024
#define CC 128
#define NW 16                 // warps per block = columns per block (incl. 2 halo)
#define TPB (NW * 32)
#define COUT (NW - 2)         // 14 output columns per block
#define ROWG 128              // rows per block

__global__ void __launch_bounds__(TPB, 2)
cos_sim_stream(const float* __restrict__ in, float* __restrict__ out)
{
    __shared__ float vs[2][NW][CC];   // double-buffered vertical-sum exchange (16 KB)

    const int lane = threadIdx.x & 31;
    const int wid  = threadIdx.x >> 5;
    const int col  = blockIdx.x * COUT + wid - 1;      // wid 0 and NW-1 are halo
    const bool colok = ((unsigned)col < (unsigned)WW);
    const bool outok = colok && (wid >= 1) && (wid <= COUT);
    const int r0 = blockIdx.y * ROWG;

    const float* gcol = in + (size_t)col * CC + lane * 4;
    const size_t rowstep = (size_t)WW * CC;

    // predicated load of pixel (h, col): this lane's 4 channels
    auto ld = [&](int h) -> float4 {
        float4 v = make_float4(0.f, 0.f, 0.f, 0.f);
        if (colok && (unsigned)h < (unsigned)HH)
            v = *reinterpret_cast<const float4*>(gcol + (size_t)h * rowstep);
        return v;
    };
    // normalize: x / max(sqrt(ss), 1e-8)
    auto normv = [&](float4 v) -> float4 {
        float ss = v.x*v.x + v.y*v.y + v.z*v.z + v.w*v.w;
        #pragma unroll
        for (int o = 16; o > 0; o >>= 1)
            ss += __shfl_xor_sync(0xffffffffu, ss, o);
        const float inv = (ss >= 1e-16f) ? rsqrtf(ss) : 1e8f;
        return make_float4(v.x*inv, v.y*inv, v.z*inv, v.w*inv);
    };

    // vertical window in registers: xnA = xn(h-1), xnB = xn(h), xnC = xn(h+1)
    float4 xnA = normv(ld(r0 - 1));
    float4 xnB = normv(ld(r0));
    float4 raw0 = ld(r0 + 1);     // two prefetch stages, 2 rows ahead
    float4 raw1 = ld(r0 + 2);
    float keep = 0.f;

    // one row step: consume a raw stage (row h+1), emit sim(h), refill stage (row h+3)
    auto step = [&](int i, float4& raw) {
        const int h = r0 + i;
        const float4 xnC = normv(raw);
        raw = ld(h + 3);

        float4 v;                                  // vertical 3-sum at (·, col)
        v.x = xnA.x + xnB.x + xnC.x;
        v.y = xnA.y + xnB.y + xnC.y;
        v.z = xnA.z + xnB.z + xnC.z;
        v.w = xnA.w + xnB.w + xnC.w;
        *reinterpret_cast<float4*>(&vs[h & 1][wid][lane * 4]) = v;
        __syncthreads();

        if (wid >= 1 && wid <= COUT) {             // warp-uniform branch
            const float4 l = *reinterpret_cast<const float4*>(&vs[h & 1][wid - 1][lane * 4]);
            const float4 r = *reinterpret_cast<const float4*>(&vs[h & 1][wid + 1][lane * 4]);
            float d;                               // xn(h,col) · 3x3-box-sum
            d =      xnB.x * (l.x + v.x + r.x);
            d = fmaf(xnB.y,  (l.y + v.y + r.y), d);
            d = fmaf(xnB.z,  (l.z + v.z + r.z), d);
            d = fmaf(xnB.w,  (l.w + v.w + r.w), d);
            #pragma unroll
            for (int o = 16; o > 0; o >>= 1)
                d += __shfl_xor_sync(0xffffffffu, d, o);

            keep = ((i & 31) == lane) ? (d - 1.0f) : keep;
            if (((i & 31) == 31) && outok)
                out[(size_t)(h - 31 + lane) * WW + col] = keep;
        }
        xnA = xnB;  xnB = xnC;
    };

    #pragma unroll 2
    for (int i = 0; i < ROWG; i += 2) {
        step(i,     raw0);
        step(i + 1, raw1);
    }
}

extern "C" void kernel_launch(void* const* d_in, const int* in_sizes, int n_in,
                              void* d_out, int out_size)
{
    const float* in = (const float*)d_in[0];
    float* out = (float*)d_out;
    dim3 grid((WW + COUT - 1) / COUT, HH / ROWG);   // 74 x 8
    cos_sim_stream<<<grid, TPB>>>(in, out);
}

// round 7
// speedup vs baseline: 3.3129x; 1.1826x over previous
#include <cuda_runtime.h>
#include <math.h>

#define HH 1024
#define WW 1024
#define CC 128
#define NW 16                 // warps per block = columns per block (incl. 2 halo)
#define TPB (NW * 32)
#define COUT (NW - 2)         // 14 output columns per block
#define ROWG 128              // rows per block
#define BATCH 32              // rows per deferred dot-reduce burst

#define VS_FLOATS (2 * 2 * NW * CC)        // 8192  (pair, rowparity, warp, ch)
#define DP_FLOATS (NW * BATCH * 33)        // 16896 (warp, rowslot, lane+pad)
#define SMEM_FLOATS (VS_FLOATS + DP_FLOATS)

// reduce TWO independent values across the warp in one shared butterfly:
// 6 SHFL total instead of 10.
__device__ __forceinline__ float2 redux2(float a, float b, int lane) {
    const unsigned full = 0xffffffffu;
    float z = (lane < 16) ? a : b;
    float w = (lane < 16) ? b : a;
    w = __shfl_xor_sync(full, w, 16);      // low half collects a, high half b
    z += w;
    #pragma unroll
    for (int o = 8; o > 0; o >>= 1)
        z += __shfl_xor_sync(full, z, o);  // reduce within each 16-lane half
    float t = __shfl_xor_sync(full, z, 16);
    float sa = (lane < 16) ? z : t;
    float sb = (lane < 16) ? t : z;
    return make_float2(sa, sb);
}

__device__ __forceinline__ float dot4(float4 v) {
    return v.x * v.x + v.y * v.y + v.z * v.z + v.w * v.w;
}

__global__ void __launch_bounds__(TPB, 2)
cos_sim_stream(const float* __restrict__ in, float* __restrict__ out)
{
    extern __shared__ float smem[];
    float* vsb = smem;                 // vertical-sum exchange ring
    float* dp  = smem + VS_FLOATS;     // per-warp deferred dot partials

    const int lane = threadIdx.x & 31;
    const int wid  = threadIdx.x >> 5;
    const int col  = blockIdx.x * COUT + wid - 1;     // wid 0 / NW-1 = halo
    const bool colok = ((unsigned)col < (unsigned)WW);
    const bool outok = colok && (wid >= 1) && (wid <= COUT);
    const int r0 = blockIdx.y * ROWG;

    float* dprow = dp + wid * (BATCH * 33);
    auto vsp = [&](int pair, int rp, int w) {
        return vsb + ((pair * 2 + rp) * NW + w) * CC;
    };

    const float* gcol = in + (size_t)col * CC + lane * 4;
    const size_t rowstep = (size_t)WW * CC;
    auto ld = [&](int h) -> float4 {
        float4 v = make_float4(0.f, 0.f, 0.f, 0.f);
        if (colok && (unsigned)h < (unsigned)HH)
            v = *reinterpret_cast<const float4*>(gcol + (size_t)h * rowstep);
        return v;
    };

    // ---- preamble: normalize rows r0-1, r0 (paired reduce); 4 rows in flight ----
    float4 xnA, xnB;
    {
        float4 ra = ld(r0 - 1), rb = ld(r0);
        float2 ss = redux2(dot4(ra), dot4(rb), lane);
        const float ia = (ss.x >= 1e-16f) ? rsqrtf(ss.x) : 1e8f;
        const float ib = (ss.y >= 1e-16f) ? rsqrtf(ss.y) : 1e8f;
        xnA = make_float4(ra.x * ia, ra.y * ia, ra.z * ia, ra.w * ia);
        xnB = make_float4(rb.x * ib, rb.y * ib, rb.z * ib, rb.w * ib);
    }
    float4 stg[2][2];
    stg[0][0] = ld(r0 + 1);  stg[0][1] = ld(r0 + 2);
    stg[1][0] = ld(r0 + 3);  stg[1][1] = ld(r0 + 4);

    #pragma unroll 2
    for (int k = 0; k < ROWG / 2; k++) {
        const int i = 2 * k;
        const int h = r0 + i;
        const int p = k & 1;

        // normalize rows h+1, h+2 with ONE paired butterfly
        float4 s0 = stg[p][0], s1 = stg[p][1];
        float2 ss = redux2(dot4(s0), dot4(s1), lane);
        const float i0 = (ss.x >= 1e-16f) ? rsqrtf(ss.x) : 1e8f;
        const float i1 = (ss.y >= 1e-16f) ? rsqrtf(ss.y) : 1e8f;
        const float4 xnC = make_float4(s0.x * i0, s0.y * i0, s0.z * i0, s0.w * i0);
        const float4 xnD = make_float4(s1.x * i1, s1.y * i1, s1.z * i1, s1.w * i1);
        stg[p][0] = ld(h + 5);                 // refill, 4 rows ahead
        stg[p][1] = ld(h + 6);

        float4 v0, v1;                         // vertical 3-sums for rows h, h+1
        v0.x = xnA.x + xnB.x + xnC.x;  v0.y = xnA.y + xnB.y + xnC.y;
        v0.z = xnA.z + xnB.z + xnC.z;  v0.w = xnA.w + xnB.w + xnC.w;
        v1.x = xnB.x + xnC.x + xnD.x;  v1.y = xnB.y + xnC.y + xnD.y;
        v1.z = xnB.z + xnC.z + xnD.z;  v1.w = xnB.w + xnC.w + xnD.w;
        *reinterpret_cast<float4*>(vsp(p, 0, wid) + lane * 4) = v0;
        *reinterpret_cast<float4*>(vsp(p, 1, wid) + lane * 4) = v1;
        __syncthreads();                       // one barrier per 2 rows

        if (wid >= 1 && wid <= COUT) {         // warp-uniform
            const float4 l0 = *reinterpret_cast<const float4*>(vsp(p, 0, wid - 1) + lane * 4);
            const float4 q0 = *reinterpret_cast<const float4*>(vsp(p, 0, wid + 1) + lane * 4);
            const float4 l1 = *reinterpret_cast<const float4*>(vsp(p, 1, wid - 1) + lane * 4);
            const float4 q1 = *reinterpret_cast<const float4*>(vsp(p, 1, wid + 1) + lane * 4);

            float d0 =       xnB.x * (l0.x + v0.x + q0.x);
            d0 = fmaf(xnB.y, (l0.y + v0.y + q0.y), d0);
            d0 = fmaf(xnB.z, (l0.z + v0.z + q0.z), d0);
            d0 = fmaf(xnB.w, (l0.w + v0.w + q0.w), d0);
            float d1 =       xnC.x * (l1.x + v1.x + q1.x);
            d1 = fmaf(xnC.y, (l1.y + v1.y + q1.y), d1);
            d1 = fmaf(xnC.z, (l1.z + v1.z + q1.z), d1);
            d1 = fmaf(xnC.w, (l1.w + v1.w + q1.w), d1);

            dprow[(i & 31) * 33 + lane]       = d0;   // defer the lane-reduction
            dprow[((i + 1) & 31) * 33 + lane] = d1;

            if ((i & 31) == 30) {              // batch of 32 rows complete
                __syncwarp();
                if (outok) {
                    float s = 0.f;
                    #pragma unroll
                    for (int j = 0; j < 32; j++) s += dprow[lane * 33 + j];
                    out[(size_t)(h - 30 + lane) * WW + col] = s - 1.0f;
                }
                __syncwarp();
            }
        }
        xnA = xnC;  xnB = xnD;
    }
}

extern "C" void kernel_launch(void* const* d_in, const int* in_sizes, int n_in,
                              void* d_out, int out_size)
{
    const float* in = (const float*)d_in[0];
    float* out = (float*)d_out;

    const size_t smem_bytes = SMEM_FLOATS * sizeof(float);   // ~98 KB
    cudaFuncSetAttribute(cos_sim_stream,
                         cudaFuncAttributeMaxDynamicSharedMemorySize,
                         (int)smem_bytes);

    dim3 grid((WW + COUT - 1) / COUT, HH / ROWG);   // 74 x 8
    cos_sim_stream<<<grid, TPB, smem_bytes>>>(in, out);
}